// round 9
// baseline (speedup 1.0000x reference)
#include <cuda_runtime.h>

// Shapes (fixed by the problem)
#define NB   4096          // batch B
#define NP   12            // P = PATCH_NUM - MASK_NUM
#define DIN  640
#define DD   128
#define MP   (NP * NB)     // 49152
#define GBLK (NB / 128)    // 32 CTAs for the global input
#define PBLK (MP / 128)    // 384 CTAs for the patch input
#define INV_T    0.25f     // 1/T, T=4
#define KL_SCALE (16.0f / 128.0f)   // T^2 / D

typedef unsigned long long ull;

// Scratch (device globals: allocation-free rule)
__device__ float d_hg[NB * DD];
__device__ float d_hp[MP * DD];
__device__ float d_g[NB * DD];
__device__ float d_p[MP * DD];
__device__ float d_part_dil[NB];
__device__ float d_part_dcl[NB];
__device__ unsigned int d_ticket;   // zero-init; self-resets each launch

// ---------------------------------------------------------------------------
// Packed fp32 FMA (SASS: FFMA2 — only reachable via PTX fma.rn.f32x2)
// ---------------------------------------------------------------------------
__device__ __forceinline__ ull ffma2(ull a, ull b, ull c)
{
    ull d;
    asm("fma.rn.f32x2 %0, %1, %2, %3;" : "=l"(d) : "l"(a), "l"(b), "l"(c));
    return d;
}
__device__ __forceinline__ float2 unpack2(ull v)
{
    float2 r;
    asm("mov.b64 {%0, %1}, %2;" : "=f"(r.x), "=f"(r.y) : "l"(v));
    return r;
}

// ---------------------------------------------------------------------------
// Fused-grid SGEMM with packed FFMA2:
//   out[m, n] = epi( sum_k A[m,k] * W[n,k] + bias[n] )
// One launch covers BOTH the global (32 CTAs) and patch (384 CTAs) inputs.
// BM=128, N=128 full width, BK=16, 256 threads, 8x8 micro-tile held as
// 8x4 f32x2 pairs (paired along n). A is stored DUPLICATED in smem so an
// FFMA2 broadcast pair is one conflict-free LDS.64 (no MOV packing).
// __launch_bounds__(256,2) caps regs at 128 -> 2 CTAs (16 warps) per SM.
// ---------------------------------------------------------------------------
template <bool RELU>
__global__ __launch_bounds__(256, 2)
void mlp_gemm(const float* __restrict__ Ag, const float* __restrict__ Ap,
              const float* __restrict__ Wg, const float* __restrict__ bg,
              const float* __restrict__ Wp, const float* __restrict__ bp,
              float* __restrict__ outg, float* __restrict__ outp, int K)
{
    const float* A; const float* W; const float* bias; float* out; int m0;
    if (blockIdx.x < GBLK) {
        A = Ag; W = Wg; bias = bg; out = outg; m0 = blockIdx.x * 128;
    } else {
        A = Ap; W = Wp; bias = bp; out = outp; m0 = (blockIdx.x - GBLK) * 128;
    }

    __shared__ float As2[16][256];  // [k][2*m]  (each A value duplicated)
    __shared__ float Ws[16][128];   // [k][n]

    const int tid  = threadIdx.x;
    const int tx   = tid & 15;      // col group (n): cols tx*8 .. tx*8+7
    const int ty   = tid >> 4;      // row group (m): rows ty*8 .. ty*8+7
    const int lrow = tid >> 2;      // 0..63
    const int kq   = tid & 3;       // 0..3  (which float4 along K)

    const float* Ap0 = A + (m0 + lrow) * K + kq * 4;
    const float* Ap1 = A + (m0 + lrow + 64) * K + kq * 4;
    const float* Wp0 = W + lrow * K + kq * 4;
    const float* Wp1 = W + (lrow + 64) * K + kq * 4;

    ull acc[8][4];                  // [m row][n pair]
#pragma unroll
    for (int i = 0; i < 8; i++)
#pragma unroll
        for (int j = 0; j < 4; j++) acc[i][j] = 0ULL;

    float4 pa0 = *(const float4*)(Ap0);
    float4 pa1 = *(const float4*)(Ap1);
    float4 pw0 = *(const float4*)(Wp0);
    float4 pw1 = *(const float4*)(Wp1);

    for (int kt = 0; kt < K; kt += 16) {
        __syncthreads();
        // A duplicated: float2(v, v) at [k][2*m]
        *(float2*)&As2[kq * 4 + 0][2 * lrow]        = make_float2(pa0.x, pa0.x);
        *(float2*)&As2[kq * 4 + 1][2 * lrow]        = make_float2(pa0.y, pa0.y);
        *(float2*)&As2[kq * 4 + 2][2 * lrow]        = make_float2(pa0.z, pa0.z);
        *(float2*)&As2[kq * 4 + 3][2 * lrow]        = make_float2(pa0.w, pa0.w);
        *(float2*)&As2[kq * 4 + 0][2 * (lrow + 64)] = make_float2(pa1.x, pa1.x);
        *(float2*)&As2[kq * 4 + 1][2 * (lrow + 64)] = make_float2(pa1.y, pa1.y);
        *(float2*)&As2[kq * 4 + 2][2 * (lrow + 64)] = make_float2(pa1.z, pa1.z);
        *(float2*)&As2[kq * 4 + 3][2 * (lrow + 64)] = make_float2(pa1.w, pa1.w);
        Ws[kq * 4 + 0][lrow]      = pw0.x;
        Ws[kq * 4 + 1][lrow]      = pw0.y;
        Ws[kq * 4 + 2][lrow]      = pw0.z;
        Ws[kq * 4 + 3][lrow]      = pw0.w;
        Ws[kq * 4 + 0][lrow + 64] = pw1.x;
        Ws[kq * 4 + 1][lrow + 64] = pw1.y;
        Ws[kq * 4 + 2][lrow + 64] = pw1.z;
        Ws[kq * 4 + 3][lrow + 64] = pw1.w;
        __syncthreads();

        if (kt + 16 < K) {
            pa0 = *(const float4*)(Ap0 + kt + 16);
            pa1 = *(const float4*)(Ap1 + kt + 16);
            pw0 = *(const float4*)(Wp0 + kt + 16);
            pw1 = *(const float4*)(Wp1 + kt + 16);
        }

#pragma unroll
        for (int k = 0; k < 16; k++) {
            // B pairs free from 128-bit loads (16B-aligned)
            const ulonglong2 bq0 = *(const ulonglong2*)(&Ws[k][tx * 8]);
            const ulonglong2 bq1 = *(const ulonglong2*)(&Ws[k][tx * 8 + 4]);
            const ull b0 = bq0.x, b1 = bq0.y, b2 = bq1.x, b3 = bq1.y;
#pragma unroll
            for (int i = 0; i < 8; i++) {
                // broadcast pair (a, a) via one LDS.64 from duplicated smem
                const ull a2 = *(const ull*)(&As2[k][2 * (ty * 8 + i)]);
                acc[i][0] = ffma2(a2, b0, acc[i][0]);
                acc[i][1] = ffma2(a2, b1, acc[i][1]);
                acc[i][2] = ffma2(a2, b2, acc[i][2]);
                acc[i][3] = ffma2(a2, b3, acc[i][3]);
            }
        }
    }

    // epilogue
    float bv[8];
#pragma unroll
    for (int j = 0; j < 8; j++) bv[j] = bias[tx * 8 + j];

#pragma unroll
    for (int i = 0; i < 8; i++) {
        float v[8];
#pragma unroll
        for (int j = 0; j < 4; j++) {
            const float2 f = unpack2(acc[i][j]);
            v[2 * j]     = f.x + bv[2 * j];
            v[2 * j + 1] = f.y + bv[2 * j + 1];
        }
        const int row = m0 + ty * 8 + i;

        if (RELU) {
            float4 o0, o1;
            o0.x = fmaxf(v[0], 0.0f); o0.y = fmaxf(v[1], 0.0f);
            o0.z = fmaxf(v[2], 0.0f); o0.w = fmaxf(v[3], 0.0f);
            o1.x = fmaxf(v[4], 0.0f); o1.y = fmaxf(v[5], 0.0f);
            o1.z = fmaxf(v[6], 0.0f); o1.w = fmaxf(v[7], 0.0f);
            *(float4*)(out + row * DD + tx * 8)     = o0;
            *(float4*)(out + row * DD + tx * 8 + 4) = o1;
        } else {
            float ss = 0.0f;
#pragma unroll
            for (int j = 0; j < 8; j++) ss = fmaf(v[j], v[j], ss);
            // reduce across the 16 lanes sharing this row (xor<16 in-group)
#pragma unroll
            for (int o = 1; o < 16; o <<= 1)
                ss += __shfl_xor_sync(0xffffffffu, ss, o);
            const float r = rsqrtf(ss);
            float4 o0, o1;
            o0.x = v[0] * r; o0.y = v[1] * r; o0.z = v[2] * r; o0.w = v[3] * r;
            o1.x = v[4] * r; o1.y = v[5] * r; o1.z = v[6] * r; o1.w = v[7] * r;
            *(float4*)(out + row * DD + tx * 8)     = o0;
            *(float4*)(out + row * DD + tx * 8 + 4) = o1;
        }
    }
}

// ---------------------------------------------------------------------------
// Symmetric KL over one D=128 row handled by one warp (4 elems / lane).
// Returns sum_d (p1 - p2) * (l1 - l2)  (== both KL directions summed).
// ---------------------------------------------------------------------------
__device__ __forceinline__ float warp_sum(float v)
{
#pragma unroll
    for (int o = 16; o > 0; o >>= 1) v += __shfl_xor_sync(0xffffffffu, v, o);
    return v;
}
__device__ __forceinline__ float warp_max(float v)
{
#pragma unroll
    for (int o = 16; o > 0; o >>= 1)
        v = fmaxf(v, __shfl_xor_sync(0xffffffffu, v, o));
    return v;
}

__device__ __forceinline__ float sym_kl(const float z1[4], const float z2[4])
{
    float m1 = fmaxf(fmaxf(z1[0], z1[1]), fmaxf(z1[2], z1[3]));
    float m2 = fmaxf(fmaxf(z2[0], z2[1]), fmaxf(z2[2], z2[3]));
    m1 = warp_max(m1);
    m2 = warp_max(m2);
    float e1[4], e2[4], s1 = 0.0f, s2 = 0.0f;
#pragma unroll
    for (int i = 0; i < 4; i++) {
        e1[i] = __expf(z1[i] - m1); s1 += e1[i];
        e2[i] = __expf(z2[i] - m2); s2 += e2[i];
    }
    s1 = warp_sum(s1);
    s2 = warp_sum(s2);
    const float inv1 = 1.0f / s1, inv2 = 1.0f / s2;
    const float c1 = m1 + __logf(s1), c2 = m2 + __logf(s2);
    float c = 0.0f;
#pragma unroll
    for (int i = 0; i < 4; i++) {
        const float l1 = z1[i] - c1;
        const float l2 = z2[i] - c2;
        c += (e1[i] * inv1 - e2[i] * inv2) * (l1 - l2);
    }
    return warp_sum(c);
}

// ---------------------------------------------------------------------------
// Fused loss: one block per b (128 threads = 4 warps).
//  - pbar[b] from the 12 p rows (each read from gmem exactly once)
//  - dil (warp 0), 12 dcl terms (3 per warp)
//  - LAST finished block performs the final reduction (fixed order ->
//    deterministic), writing out[0] = dil, out[1] = dcl.
// ---------------------------------------------------------------------------
__global__ __launch_bounds__(128) void loss_kernel(float* __restrict__ out)
{
    __shared__ float sp[NP][DD];   // 12 p rows
    __shared__ float sg[DD];
    __shared__ float spb[DD];
    __shared__ float wpart[4];
    __shared__ int   amLast;

    const int b    = blockIdx.x;
    const int tid  = threadIdx.x;      // == d
    const int w    = tid >> 5;
    const int lane = tid & 31;

    // stage data, compute pbar
    sg[tid] = d_g[b * DD + tid];
    float s = 0.0f;
#pragma unroll
    for (int l = 0; l < NP; l++) {
        const float pv = d_p[(l * NB + b) * DD + tid];
        sp[l][tid] = pv;
        s += pv;
    }
    spb[tid] = s * (1.0f / 12.0f);
    __syncthreads();

    // dcl: warp w handles l = 3w .. 3w+2
    float gv[4], pbv[4];
#pragma unroll
    for (int i = 0; i < 4; i++) {
        gv[i]  = sg[lane + 32 * i];
        pbv[i] = spb[lane + 32 * i];
    }

    float dcl = 0.0f;
#pragma unroll
    for (int t = 0; t < 3; t++) {
        const int l = w * 3 + t;
        float z1[4], z2[4];
#pragma unroll
        for (int i = 0; i < 4; i++) {
            const float pv = sp[l][lane + 32 * i];
            const float t1 = gv[i] - pv;
            const float t2 = pbv[i] - pv;
            z1[i] = t1 * t1 * INV_T;
            z2[i] = t2 * t2 * INV_T;
        }
        dcl += sym_kl(z1, z2);
    }
    if (lane == 0) wpart[w] = dcl * KL_SCALE;

    // dil: warp 0
    if (w == 0) {
        float z1[4], z2[4];
#pragma unroll
        for (int i = 0; i < 4; i++) {
            z1[i] = gv[i] * INV_T;
            z2[i] = pbv[i] * INV_T;
        }
        const float dil = sym_kl(z1, z2) * KL_SCALE;
        if (lane == 0) d_part_dil[b] = dil;
    }
    __syncthreads();

    if (tid == 0) {
        d_part_dcl[b] = wpart[0] + wpart[1] + wpart[2] + wpart[3];
        __threadfence();
        amLast = (atomicAdd(&d_ticket, 1u) == (unsigned)(NB - 1));
    }
    __syncthreads();

    // Final reduction by the last-finishing block. Fixed accumulation order
    // (strided per-thread, then fixed tree) -> bitwise deterministic.
    if (amLast) {
        __shared__ float r1[128], r2[128];
        float a = 0.0f, c = 0.0f;
        for (int i = tid; i < NB; i += 128) {
            a += d_part_dil[i];
            c += d_part_dcl[i];
        }
        r1[tid] = a; r2[tid] = c;
        __syncthreads();
        for (int o = 64; o > 0; o >>= 1) {
            if (tid < o) { r1[tid] += r1[tid + o]; r2[tid] += r2[tid + o]; }
            __syncthreads();
        }
        if (tid == 0) {
            out[0] = r1[0];
            out[1] = r2[0] * (1.0f / 12.0f);
            d_ticket = 0;   // reset for next graph replay
        }
    }
}

// ---------------------------------------------------------------------------
// Launch
// Inputs (metadata order): ebg, ebp, labelsg, glo_w1, glo_b1, glo_w2, glo_b2,
//                          pat_w1, pat_b1, pat_w2, pat_b2
// ---------------------------------------------------------------------------
extern "C" void kernel_launch(void* const* d_in, const int* in_sizes, int n_in,
                              void* d_out, int out_size)
{
    const float* ebg    = (const float*)d_in[0];
    const float* ebp    = (const float*)d_in[1];
    const float* glo_w1 = (const float*)d_in[3];
    const float* glo_b1 = (const float*)d_in[4];
    const float* glo_w2 = (const float*)d_in[5];
    const float* glo_b2 = (const float*)d_in[6];
    const float* pat_w1 = (const float*)d_in[7];
    const float* pat_b1 = (const float*)d_in[8];
    const float* pat_w2 = (const float*)d_in[9];
    const float* pat_b2 = (const float*)d_in[10];
    float* out = (float*)d_out;

    float *hg, *hp, *g, *p;
    cudaGetSymbolAddress((void**)&hg, d_hg);
    cudaGetSymbolAddress((void**)&hp, d_hp);
    cudaGetSymbolAddress((void**)&g,  d_g);
    cudaGetSymbolAddress((void**)&p,  d_p);

    // Layer 1 (K=640) + ReLU — one grid covers global (32) + patch (384)
    mlp_gemm<true><<<GBLK + PBLK, 256>>>(ebg, ebp, glo_w1, glo_b1,
                                         pat_w1, pat_b1, hg, hp, DIN);
    // Layer 2 (K=128) + bias + L2 normalize
    mlp_gemm<false><<<GBLK + PBLK, 256>>>(hg, hp, glo_w2, glo_b2,
                                          pat_w2, pat_b2, g, p, DD);
    // Fused pbar + dil + dcl + final reduction (last block)
    loss_kernel<<<NB, 128>>>(out);
}

// round 12
// speedup vs baseline: 1.4911x; 1.4911x over previous
#include <cuda_runtime.h>

// Shapes (fixed by the problem)
#define NB   4096          // batch B
#define NP   12            // P = PATCH_NUM - MASK_NUM
#define DIN  640
#define DD   128
#define MP   (NP * NB)     // 49152
#define GBLK (NB / 128)    // 32 CTAs for the global input
#define PBLK (MP / 128)    // 384 CTAs for the patch input
#define INV_T    0.25f     // 1/T, T=4
#define KL_SCALE (16.0f / 128.0f)   // T^2 / D

// Scratch (device globals: allocation-free rule)
__device__ float d_hg[NB * DD];
__device__ float d_hp[MP * DD];
__device__ float d_g[NB * DD];
__device__ float d_p[MP * DD];
__device__ float d_part_dil[NB];
__device__ float d_part_dcl[NB];
__device__ unsigned int d_ticket;   // zero-init; self-resets each launch

// ---------------------------------------------------------------------------
// TF32 helpers
// ---------------------------------------------------------------------------
__device__ __forceinline__ float tf32_rn(float v)
{
    unsigned r;
    asm("cvt.rna.tf32.f32 %0, %1;" : "=r"(r) : "f"(v));
    return __uint_as_float(r);
}

// mma.m16n8k8 tf32: D = A(16x8) * B(8x8) + D, fp32 accum
#define MMA_TF32(c, a, b)                                                     \
    asm("mma.sync.aligned.m16n8k8.row.col.f32.tf32.tf32.f32 "                 \
        "{%0,%1,%2,%3}, {%4,%5,%6,%7}, {%8,%9}, {%0,%1,%2,%3};"               \
        : "+f"((c)[0]), "+f"((c)[1]), "+f"((c)[2]), "+f"((c)[3])              \
        : "r"((a)[0]), "r"((a)[1]), "r"((a)[2]), "r"((a)[3]),                 \
          "r"((b)[0]), "r"((b)[1]))

// split v into hi/lo tf32 parts and store both float4s
__device__ __forceinline__ void split_sts(float* hi, float* lo, float4 v)
{
    float4 h, l;
    h.x = tf32_rn(v.x); l.x = tf32_rn(v.x - h.x);
    h.y = tf32_rn(v.y); l.y = tf32_rn(v.y - h.y);
    h.z = tf32_rn(v.z); l.z = tf32_rn(v.z - h.z);
    h.w = tf32_rn(v.w); l.w = tf32_rn(v.w - h.w);
    *(float4*)hi = h;
    *(float4*)lo = l;
}

// ---------------------------------------------------------------------------
// Fused-grid TF32 GEMM (3xTF32): out[m,n] = epi( sum_k A[m,k]*W[n,k] + b[n] )
// One launch covers BOTH the global (32 CTAs) and patch (384 CTAs) inputs.
// BM=128, BN=128 (full width), BK=16, 256 threads = 8 warps (4 m x 2 n),
// warp tile 32x64 = 2x8 mma(16x8) tiles. A/W split hi/lo in smem.
// smem rows padded to 20 words -> fragment LDS conflict-free.
// ---------------------------------------------------------------------------
template <bool RELU>
__global__ __launch_bounds__(256, 2)
void mlp_gemm(const float* __restrict__ Ag, const float* __restrict__ Ap,
              const float* __restrict__ Wg, const float* __restrict__ bg,
              const float* __restrict__ Wp, const float* __restrict__ bp,
              float* __restrict__ outg, float* __restrict__ outp, int K)
{
    const float* A; const float* W; const float* bias; float* out; int m0;
    if (blockIdx.x < GBLK) {
        A = Ag; W = Wg; bias = bg; out = outg; m0 = blockIdx.x * 128;
    } else {
        A = Ap; W = Wp; bias = bp; out = outp; m0 = (blockIdx.x - GBLK) * 128;
    }

    __shared__ float Ah[128][20];   // [m][k] hi, 4-word pad
    __shared__ float Al[128][20];   // [m][k] lo
    __shared__ float Wh[128][20];   // [n][k] hi
    __shared__ float Wl[128][20];   // [n][k] lo

    const int tid    = threadIdx.x;
    const int lane   = tid & 31;
    const int wid    = tid >> 5;
    const int warp_m = wid & 3;     // m offset = warp_m*32
    const int warp_n = wid >> 2;    // n offset = warp_n*64
    const int gid    = lane >> 2;   // 0..7
    const int tq     = lane & 3;    // 0..3

    const int lrow = tid >> 2;      // 0..63 (loader row)
    const int kq   = tid & 3;       // which float4 along K

    const float* Apt0 = A + (m0 + lrow) * K + kq * 4;
    const float* Apt1 = A + (m0 + lrow + 64) * K + kq * 4;
    const float* Wpt0 = W + lrow * K + kq * 4;
    const float* Wpt1 = W + (lrow + 64) * K + kq * 4;

    float acc[2][8][4];             // [m tile][n tile][c frag]
#pragma unroll
    for (int i = 0; i < 2; i++)
#pragma unroll
        for (int j = 0; j < 8; j++)
#pragma unroll
            for (int q = 0; q < 4; q++) acc[i][j][q] = 0.0f;

    float4 pa0 = *(const float4*)(Apt0);
    float4 pa1 = *(const float4*)(Apt1);
    float4 pw0 = *(const float4*)(Wpt0);
    float4 pw1 = *(const float4*)(Wpt1);

    for (int kt = 0; kt < K; kt += 16) {
        __syncthreads();
        split_sts(&Ah[lrow][kq * 4],      &Al[lrow][kq * 4],      pa0);
        split_sts(&Ah[lrow + 64][kq * 4], &Al[lrow + 64][kq * 4], pa1);
        split_sts(&Wh[lrow][kq * 4],      &Wl[lrow][kq * 4],      pw0);
        split_sts(&Wh[lrow + 64][kq * 4], &Wl[lrow + 64][kq * 4], pw1);
        __syncthreads();

        if (kt + 16 < K) {
            pa0 = *(const float4*)(Apt0 + kt + 16);
            pa1 = *(const float4*)(Apt1 + kt + 16);
            pw0 = *(const float4*)(Wpt0 + kt + 16);
            pw1 = *(const float4*)(Wpt1 + kt + 16);
        }

#pragma unroll
        for (int s = 0; s < 2; s++) {           // two k8 steps per stage
            const int k0 = s * 8;

            // A fragments (both m tiles), hi and lo
            unsigned ah[2][4], al[2][4];
#pragma unroll
            for (int mt = 0; mt < 2; mt++) {
                const int rA = warp_m * 32 + mt * 16;
                ah[mt][0] = __float_as_uint(Ah[rA + gid]    [k0 + tq]);
                ah[mt][1] = __float_as_uint(Ah[rA + gid + 8][k0 + tq]);
                ah[mt][2] = __float_as_uint(Ah[rA + gid]    [k0 + tq + 4]);
                ah[mt][3] = __float_as_uint(Ah[rA + gid + 8][k0 + tq + 4]);
                al[mt][0] = __float_as_uint(Al[rA + gid]    [k0 + tq]);
                al[mt][1] = __float_as_uint(Al[rA + gid + 8][k0 + tq]);
                al[mt][2] = __float_as_uint(Al[rA + gid]    [k0 + tq + 4]);
                al[mt][3] = __float_as_uint(Al[rA + gid + 8][k0 + tq + 4]);
            }

#pragma unroll
            for (int half = 0; half < 2; half++) {   // n tiles in 2 groups of 4
                unsigned bh[4][2], bl[4][2];
#pragma unroll
                for (int j = 0; j < 4; j++) {
                    const int cB = warp_n * 64 + (half * 4 + j) * 8;
                    bh[j][0] = __float_as_uint(Wh[cB + gid][k0 + tq]);
                    bh[j][1] = __float_as_uint(Wh[cB + gid][k0 + tq + 4]);
                    bl[j][0] = __float_as_uint(Wl[cB + gid][k0 + tq]);
                    bl[j][1] = __float_as_uint(Wl[cB + gid][k0 + tq + 4]);
                }
                // 3 passes: hi*hi, lo*hi, hi*lo (8 independent mmas per pass)
#pragma unroll
                for (int p = 0; p < 3; p++) {
#pragma unroll
                    for (int mt = 0; mt < 2; mt++)
#pragma unroll
                        for (int j = 0; j < 4; j++) {
                            const unsigned* aa = (p == 1) ? al[mt] : ah[mt];
                            const unsigned* bb = (p == 2) ? bl[j]  : bh[j];
                            MMA_TF32(acc[mt][half * 4 + j], aa, bb);
                        }
                }
            }
        }
    }

    // -------------------------- epilogue -----------------------------------
    // thread owns rows r0 = warp_m*32 + mt*16 + gid, r1 = r0 + 8
    // cols  col(nt) = warp_n*64 + nt*8 + tq*2  (c0,c1) ; same for (c2,c3)
    float2 bb[8];
#pragma unroll
    for (int nt = 0; nt < 8; nt++)
        bb[nt] = *(const float2*)&bias[warp_n * 64 + nt * 8 + tq * 2];

    if (RELU) {
#pragma unroll
        for (int mt = 0; mt < 2; mt++) {
            const int r0 = m0 + warp_m * 32 + mt * 16 + gid;
#pragma unroll
            for (int nt = 0; nt < 8; nt++) {
                const int col = warp_n * 64 + nt * 8 + tq * 2;
                float2 v0, v1;
                v0.x = fmaxf(acc[mt][nt][0] + bb[nt].x, 0.0f);
                v0.y = fmaxf(acc[mt][nt][1] + bb[nt].y, 0.0f);
                v1.x = fmaxf(acc[mt][nt][2] + bb[nt].x, 0.0f);
                v1.y = fmaxf(acc[mt][nt][3] + bb[nt].y, 0.0f);
                *(float2*)(out + r0 * DD + col)       = v0;
                *(float2*)(out + (r0 + 8) * DD + col) = v1;
            }
        }
    } else {
        // + bias, then L2-normalize each row of the 128x128 tile
#pragma unroll
        for (int mt = 0; mt < 2; mt++)
#pragma unroll
            for (int nt = 0; nt < 8; nt++) {
                acc[mt][nt][0] += bb[nt].x;
                acc[mt][nt][1] += bb[nt].y;
                acc[mt][nt][2] += bb[nt].x;
                acc[mt][nt][3] += bb[nt].y;
            }

        float s0[2], s1[2];
#pragma unroll
        for (int mt = 0; mt < 2; mt++) {
            float a = 0.0f, c = 0.0f;
#pragma unroll
            for (int nt = 0; nt < 8; nt++) {
                a = fmaf(acc[mt][nt][0], acc[mt][nt][0], a);
                a = fmaf(acc[mt][nt][1], acc[mt][nt][1], a);
                c = fmaf(acc[mt][nt][2], acc[mt][nt][2], c);
                c = fmaf(acc[mt][nt][3], acc[mt][nt][3], c);
            }
            s0[mt] = a; s1[mt] = c;
        }
        // reduce over the 4 lanes of the quad (same gid)
#pragma unroll
        for (int o = 1; o < 4; o <<= 1) {
#pragma unroll
            for (int mt = 0; mt < 2; mt++) {
                s0[mt] += __shfl_xor_sync(0xffffffffu, s0[mt], o);
                s1[mt] += __shfl_xor_sync(0xffffffffu, s1[mt], o);
            }
        }
        // cross-warp (warp_n 0/1) combine via smem (reuse Ah storage)
        float* rsbuf = &Ah[0][0];   // 256 floats used
        __syncthreads();            // mainloop smem reads complete
        if (tq == 0) {
#pragma unroll
            for (int mt = 0; mt < 2; mt++) {
                const int lr0 = warp_m * 32 + mt * 16 + gid;
                rsbuf[lr0 * 2 + warp_n]       = s0[mt];
                rsbuf[(lr0 + 8) * 2 + warp_n] = s1[mt];
            }
        }
        __syncthreads();
#pragma unroll
        for (int mt = 0; mt < 2; mt++) {
            const int lr0 = warp_m * 32 + mt * 16 + gid;
            const float inv0 = rsqrtf(rsbuf[lr0 * 2] + rsbuf[lr0 * 2 + 1]);
            const float inv1 = rsqrtf(rsbuf[(lr0 + 8) * 2] + rsbuf[(lr0 + 8) * 2 + 1]);
            const int r0 = m0 + lr0;
#pragma unroll
            for (int nt = 0; nt < 8; nt++) {
                const int col = warp_n * 64 + nt * 8 + tq * 2;
                float2 v0, v1;
                v0.x = acc[mt][nt][0] * inv0;
                v0.y = acc[mt][nt][1] * inv0;
                v1.x = acc[mt][nt][2] * inv1;
                v1.y = acc[mt][nt][3] * inv1;
                *(float2*)(out + r0 * DD + col)       = v0;
                *(float2*)(out + (r0 + 8) * DD + col) = v1;
            }
        }
    }
}

// ---------------------------------------------------------------------------
// Symmetric KL over one D=128 row handled by one warp (4 elems / lane).
// Returns sum_d (p1 - p2) * (l1 - l2)  (== both KL directions summed).
// ---------------------------------------------------------------------------
__device__ __forceinline__ float warp_sum(float v)
{
#pragma unroll
    for (int o = 16; o > 0; o >>= 1) v += __shfl_xor_sync(0xffffffffu, v, o);
    return v;
}
__device__ __forceinline__ float warp_max(float v)
{
#pragma unroll
    for (int o = 16; o > 0; o >>= 1)
        v = fmaxf(v, __shfl_xor_sync(0xffffffffu, v, o));
    return v;
}

__device__ __forceinline__ float sym_kl(const float z1[4], const float z2[4])
{
    float m1 = fmaxf(fmaxf(z1[0], z1[1]), fmaxf(z1[2], z1[3]));
    float m2 = fmaxf(fmaxf(z2[0], z2[1]), fmaxf(z2[2], z2[3]));
    m1 = warp_max(m1);
    m2 = warp_max(m2);
    float e1[4], e2[4], s1 = 0.0f, s2 = 0.0f;
#pragma unroll
    for (int i = 0; i < 4; i++) {
        e1[i] = __expf(z1[i] - m1); s1 += e1[i];
        e2[i] = __expf(z2[i] - m2); s2 += e2[i];
    }
    s1 = warp_sum(s1);
    s2 = warp_sum(s2);
    const float inv1 = 1.0f / s1, inv2 = 1.0f / s2;
    const float c1 = m1 + __logf(s1), c2 = m2 + __logf(s2);
    float c = 0.0f;
#pragma unroll
    for (int i = 0; i < 4; i++) {
        const float l1 = z1[i] - c1;
        const float l2 = z2[i] - c2;
        c += (e1[i] * inv1 - e2[i] * inv2) * (l1 - l2);
    }
    return warp_sum(c);
}

// ---------------------------------------------------------------------------
// Fused loss: one block per b (128 threads = 4 warps).
//  - pbar[b] from the 12 p rows (each read from gmem exactly once)
//  - dil (warp 0), 12 dcl terms (3 per warp)
//  - LAST finished block performs the final reduction (fixed order ->
//    deterministic), writing out[0] = dil, out[1] = dcl.
// ---------------------------------------------------------------------------
__global__ __launch_bounds__(128) void loss_kernel(float* __restrict__ out)
{
    __shared__ float sp[NP][DD];   // 12 p rows
    __shared__ float sg[DD];
    __shared__ float spb[DD];
    __shared__ float wpart[4];
    __shared__ int   amLast;

    const int b    = blockIdx.x;
    const int tid  = threadIdx.x;      // == d
    const int w    = tid >> 5;
    const int lane = tid & 31;

    // stage data, compute pbar
    sg[tid] = d_g[b * DD + tid];
    float s = 0.0f;
#pragma unroll
    for (int l = 0; l < NP; l++) {
        const float pv = d_p[(l * NB + b) * DD + tid];
        sp[l][tid] = pv;
        s += pv;
    }
    spb[tid] = s * (1.0f / 12.0f);
    __syncthreads();

    // dcl: warp w handles l = 3w .. 3w+2
    float gv[4], pbv[4];
#pragma unroll
    for (int i = 0; i < 4; i++) {
        gv[i]  = sg[lane + 32 * i];
        pbv[i] = spb[lane + 32 * i];
    }

    float dcl = 0.0f;
#pragma unroll
    for (int t = 0; t < 3; t++) {
        const int l = w * 3 + t;
        float z1[4], z2[4];
#pragma unroll
        for (int i = 0; i < 4; i++) {
            const float pv = sp[l][lane + 32 * i];
            const float t1 = gv[i] - pv;
            const float t2 = pbv[i] - pv;
            z1[i] = t1 * t1 * INV_T;
            z2[i] = t2 * t2 * INV_T;
        }
        dcl += sym_kl(z1, z2);
    }
    if (lane == 0) wpart[w] = dcl * KL_SCALE;

    // dil: warp 0
    if (w == 0) {
        float z1[4], z2[4];
#pragma unroll
        for (int i = 0; i < 4; i++) {
            z1[i] = gv[i] * INV_T;
            z2[i] = pbv[i] * INV_T;
        }
        const float dil = sym_kl(z1, z2) * KL_SCALE;
        if (lane == 0) d_part_dil[b] = dil;
    }
    __syncthreads();

    if (tid == 0) {
        d_part_dcl[b] = wpart[0] + wpart[1] + wpart[2] + wpart[3];
        __threadfence();
        amLast = (atomicAdd(&d_ticket, 1u) == (unsigned)(NB - 1));
    }
    __syncthreads();

    // Final reduction by the last-finishing block. Fixed accumulation order
    // (strided per-thread, then fixed tree) -> bitwise deterministic.
    if (amLast) {
        __shared__ float r1[128], r2[128];
        float a = 0.0f, c = 0.0f;
        for (int i = tid; i < NB; i += 128) {
            a += d_part_dil[i];
            c += d_part_dcl[i];
        }
        r1[tid] = a; r2[tid] = c;
        __syncthreads();
        for (int o = 64; o > 0; o >>= 1) {
            if (tid < o) { r1[tid] += r1[tid + o]; r2[tid] += r2[tid + o]; }
            __syncthreads();
        }
        if (tid == 0) {
            out[0] = r1[0];
            out[1] = r2[0] * (1.0f / 12.0f);
            d_ticket = 0;   // reset for next graph replay
        }
    }
}

// ---------------------------------------------------------------------------
// Launch
// Inputs (metadata order): ebg, ebp, labelsg, glo_w1, glo_b1, glo_w2, glo_b2,
//                          pat_w1, pat_b1, pat_w2, pat_b2
// ---------------------------------------------------------------------------
extern "C" void kernel_launch(void* const* d_in, const int* in_sizes, int n_in,
                              void* d_out, int out_size)
{
    const float* ebg    = (const float*)d_in[0];
    const float* ebp    = (const float*)d_in[1];
    const float* glo_w1 = (const float*)d_in[3];
    const float* glo_b1 = (const float*)d_in[4];
    const float* glo_w2 = (const float*)d_in[5];
    const float* glo_b2 = (const float*)d_in[6];
    const float* pat_w1 = (const float*)d_in[7];
    const float* pat_b1 = (const float*)d_in[8];
    const float* pat_w2 = (const float*)d_in[9];
    const float* pat_b2 = (const float*)d_in[10];
    float* out = (float*)d_out;

    float *hg, *hp, *g, *p;
    cudaGetSymbolAddress((void**)&hg, d_hg);
    cudaGetSymbolAddress((void**)&hp, d_hp);
    cudaGetSymbolAddress((void**)&g,  d_g);
    cudaGetSymbolAddress((void**)&p,  d_p);

    // Layer 1 (K=640) + ReLU — one grid covers global (32) + patch (384)
    mlp_gemm<true><<<GBLK + PBLK, 256>>>(ebg, ebp, glo_w1, glo_b1,
                                         pat_w1, pat_b1, hg, hp, DIN);
    // Layer 2 (K=128) + bias + L2 normalize
    mlp_gemm<false><<<GBLK + PBLK, 256>>>(hg, hp, glo_w2, glo_b2,
                                          pat_w2, pat_b2, g, p, DD);
    // Fused pbar + dil + dcl + final reduction (last block)
    loss_kernel<<<NB, 128>>>(out);
}